// round 1
// baseline (speedup 1.0000x reference)
#include <cuda_runtime.h>

#define NT 512

// ---- shared-memory layout (float offsets, all multiples of 4 for float4) ----
#define OFF_E0 0        // ext buf L=16384 : 16384+38 -> 16424
#define OFF_E1 16424    // ext buf L=8199  : 8199+38  -> 8240
#define OFF_E2 24664    // ext buf L=4107  : 4107+38  -> 4148
#define OFF_E3 28812    // ext buf L=2061  : 2061+38  -> 2100
#define OFF_A4 30912    // approx lvl4 1038 (+pad)    -> 1044
#define OFF_D1 31956    // 8199 (+pad) -> 8204
#define OFF_D2 40160    // 4107 (+pad) -> 4112
#define OFF_D3 44272    // 2061 (+pad) -> 2068
#define OFF_D4 46340    // 1038 (+pad) -> 1044
#define OFF_HIST 47384  // 256 ints histogram + 2 scalars
#define SMEM_FLOATS (47384 + 260)
#define SMEM_BYTES  (SMEM_FLOATS * 4)

#define DECL_H const float H[16] = { \
    0.05441584224308161f,  0.3128715909144659f,   0.6756307362980128f,    0.5853546836548691f, \
   -0.015829105256023893f,-0.2840155429624281f,   0.00047248457399797254f,0.128747426620186f, \
   -0.01736930100202211f, -0.04408825393106472f,  0.013981027917015516f,  0.008746094047015655f, \
   -0.00487035299301066f, -0.0003917403729959771f,0.0006754494059985568f,-0.00011747678400228192f }

// Forward DWT one level.
// Ein: shifted symmetric extension, E[m] = a[m-14] (interior m in [14, L+13],
// borders prefilled). Writes ca into caout (+14 offset if ext_out, plus border
// refill), cd into D. Output length Lc = (L+15)>>1.
__device__ __forceinline__ void fwd_level(const float* __restrict__ Ein,
                                          float* __restrict__ caout,
                                          float* __restrict__ D,
                                          int L, int ext_out, int tid)
{
    DECL_H;
    const int Lc    = (L + 15) >> 1;
    const int npair = (Lc + 1) >> 1;
    const int caoff = ext_out ? 14 : 0;
    for (int u = tid; u < npair; u += NT) {
        const float4* p = (const float4*)(Ein + 4 * u);
        float4 q0 = p[0], q1 = p[1], q2 = p[2], q3 = p[3], q4 = p[4];
        float e[20] = { q0.x,q0.y,q0.z,q0.w, q1.x,q1.y,q1.z,q1.w,
                        q2.x,q2.y,q2.z,q2.w, q3.x,q3.y,q3.z,q3.w,
                        q4.x,q4.y,q4.z,q4.w };
        float ca0 = 0.f, cd0 = 0.f, ca1 = 0.f, cd1 = 0.f;
        #pragma unroll
        for (int i = 0; i < 16; i++) {
            const float g = ((i & 1) ? -H[15 - i] : H[15 - i]);   // (-1)^i * H[15-i]
            ca0 += H[i] * e[i];     cd0 += g * e[i];
            ca1 += H[i] * e[i + 2]; cd1 += g * e[i + 2];
        }
        caout[caoff + 2 * u] = ca0;
        D[2 * u] = cd0;
        if (2 * u + 1 < Lc) { caout[caoff + 2 * u + 1] = ca1; D[2 * u + 1] = cd1; }
    }
    __syncthreads();
    if (ext_out) {
        // rebuild symmetric borders of the freshly written ext buffer
        if (tid < 14)      caout[tid] = caout[27 - tid];
        else if (tid < 30) { int m = Lc + tid; caout[m] = caout[2 * Lc + 27 - m]; }
        __syncthreads();
    }
}

// Inverse DWT one level into shared memory. No boundary handling needed
// (slice [F-2:2n] keeps only full-support outputs). 8 outputs per thread-iter.
__device__ __forceinline__ void inv_level(const float* __restrict__ ca,
                                          const float* __restrict__ cd,
                                          float* __restrict__ outsh,
                                          int n_out, int tid)
{
    DECL_H;
    const int nu = (n_out + 7) >> 3;
    for (int u = tid; u < nu; u += NT) {
        const float4* pa = (const float4*)(ca + 4 * u);
        const float4* pc = (const float4*)(cd + 4 * u);
        float4 a0 = pa[0], a1 = pa[1], a2 = pa[2];
        float4 c0 = pc[0], c1 = pc[1], c2 = pc[2];
        float A[12] = { a0.x,a0.y,a0.z,a0.w, a1.x,a1.y,a1.z,a1.w, a2.x,a2.y,a2.z,a2.w };
        float C[12] = { c0.x,c0.y,c0.z,c0.w, c1.x,c1.y,c1.z,c1.w, c2.x,c2.y,c2.z,c2.w };
        float r[8];
        #pragma unroll
        for (int j = 0; j < 4; j++) {
            float re = 0.f, ro = 0.f;
            #pragma unroll
            for (int i = 0; i < 8; i++) {
                re += H[14 - 2 * i] * A[j + i] + H[2 * i + 1] * C[j + i];
                ro += H[15 - 2 * i] * A[j + i] - H[2 * i]     * C[j + i];
            }
            r[2 * j]     = re;
            r[2 * j + 1] = ro;
        }
        const int base = 8 * u;
        #pragma unroll
        for (int j = 0; j < 8; j++)
            if (base + j < n_out) outsh[base + j] = r[j];
    }
    __syncthreads();
}

// Final inverse level: n_out = 16384 exactly, write straight to gmem (float4).
__device__ __forceinline__ void inv_final(const float* __restrict__ ca,
                                          const float* __restrict__ cd,
                                          float* __restrict__ gout, int tid)
{
    DECL_H;
    for (int u = tid; u < 2048; u += NT) {
        const float4* pa = (const float4*)(ca + 4 * u);
        const float4* pc = (const float4*)(cd + 4 * u);
        float4 a0 = pa[0], a1 = pa[1], a2 = pa[2];
        float4 c0 = pc[0], c1 = pc[1], c2 = pc[2];
        float A[12] = { a0.x,a0.y,a0.z,a0.w, a1.x,a1.y,a1.z,a1.w, a2.x,a2.y,a2.z,a2.w };
        float C[12] = { c0.x,c0.y,c0.z,c0.w, c1.x,c1.y,c1.z,c1.w, c2.x,c2.y,c2.z,c2.w };
        float r[8];
        #pragma unroll
        for (int j = 0; j < 4; j++) {
            float re = 0.f, ro = 0.f;
            #pragma unroll
            for (int i = 0; i < 8; i++) {
                re += H[14 - 2 * i] * A[j + i] + H[2 * i + 1] * C[j + i];
                ro += H[15 - 2 * i] * A[j + i] - H[2 * i]     * C[j + i];
            }
            r[2 * j]     = re;
            r[2 * j + 1] = ro;
        }
        float4* po = (float4*)(gout + 8 * u);
        po[0] = make_float4(r[0], r[1], r[2], r[3]);
        po[1] = make_float4(r[4], r[5], r[6], r[7]);
    }
}

__global__ void __launch_bounds__(NT, 1)
wden_kernel(const float* __restrict__ x, float* __restrict__ out, int rows)
{
    extern __shared__ float sm[];
    const int tid = threadIdx.x;
    const int row = blockIdx.x;
    if (row >= rows) return;

    float* E0 = sm + OFF_E0;  float* E1 = sm + OFF_E1;
    float* E2 = sm + OFF_E2;  float* E3 = sm + OFF_E3;
    float* A4 = sm + OFF_A4;
    float* D1 = sm + OFF_D1;  float* D2 = sm + OFF_D2;
    float* D3 = sm + OFF_D3;  float* D4 = sm + OFF_D4;
    int*   hist = (int*)(sm + OFF_HIST);

    const float* xr = x + (size_t)row * 16384;

    // load row into E0 interior (E0[14 + i] = x[i]) + symmetric borders
    for (int i = tid; i < 4096; i += NT) {
        float4 v = ((const float4*)xr)[i];
        *(float2*)(E0 + 14 + 4 * i) = make_float2(v.x, v.y);
        *(float2*)(E0 + 16 + 4 * i) = make_float2(v.z, v.w);
    }
    if (tid < 14)      E0[tid] = xr[13 - tid];
    else if (tid < 30) { int m = 16384 + tid; E0[m] = xr[32781 - m]; }
    __syncthreads();

    // forward DWT: 16384 -> 8199 -> 4107 -> 2061 -> 1038
    fwd_level(E0, E1, D1, 16384, 1, tid);
    fwd_level(E1, E2, D2, 8199,  1, tid);
    fwd_level(E2, E3, D3, 4107,  1, tid);
    fwd_level(E3, A4, D4, 2061,  0, tid);

    // median(|D1|): rank 4099 of 8199, 4-round MSB radix select on float bits
    unsigned pref = 0; int kk = 4099;
    for (int round = 0; round < 4; round++) {
        const int shift = 24 - 8 * round;
        const unsigned hmask = (round == 0) ? 0u : (0xFFFFFFFFu << (shift + 8));
        for (int i = tid; i < 256; i += NT) hist[i] = 0;
        __syncthreads();
        for (int i = tid; i < 8199; i += NT) {
            unsigned b = __float_as_uint(fabsf(D1[i]));
            if ((b & hmask) == pref) atomicAdd(&hist[(b >> shift) & 255], 1);
        }
        __syncthreads();
        if (tid == 0) {
            int acc = 0, b = 0;
            for (; b < 255; b++) { int c = hist[b]; if (acc + c > kk) break; acc += c; }
            hist[256] = (int)(pref | ((unsigned)b << shift));
            hist[257] = kk - acc;
        }
        __syncthreads();
        pref = (unsigned)hist[256];
        kk   = hist[257];
        __syncthreads();
    }
    const float med = __uint_as_float(pref);
    const float thr = (med / 0.6745f) * 4.4054649f;   // sqrt(2*ln(16384))

    // soft-threshold all detail bands in place
    for (int i = tid; i < 8199; i += NT) { float v = D1[i]; float a = fabsf(v) - thr; D1[i] = a > 0.f ? copysignf(a, v) : 0.f; }
    for (int i = tid; i < 4107; i += NT) { float v = D2[i]; float a = fabsf(v) - thr; D2[i] = a > 0.f ? copysignf(a, v) : 0.f; }
    for (int i = tid; i < 2061; i += NT) { float v = D3[i]; float a = fabsf(v) - thr; D3[i] = a > 0.f ? copysignf(a, v) : 0.f; }
    for (int i = tid; i < 1038; i += NT) { float v = D4[i]; float a = fabsf(v) - thr; D4[i] = a > 0.f ? copysignf(a, v) : 0.f; }
    __syncthreads();

    // inverse DWT: 1038 -> 2061 -> 4107 -> 8199 -> 16384 (reuse dead ext bufs)
    inv_level(A4, D4, E3, 2061, tid);
    inv_level(E3, D3, E2, 4107, tid);
    inv_level(E2, D2, E1, 8199, tid);
    inv_final(E1, D1, out + (size_t)row * 16384, tid);
}

extern "C" void kernel_launch(void* const* d_in, const int* in_sizes, int n_in,
                              void* d_out, int out_size)
{
    const float* x = (const float*)d_in[0];
    float* out = (float*)d_out;
    const int rows = in_sizes[0] / 16384;   // 128*16 = 2048
    cudaFuncSetAttribute(wden_kernel, cudaFuncAttributeMaxDynamicSharedMemorySize, SMEM_BYTES);
    wden_kernel<<<rows, NT, SMEM_BYTES>>>(x, out, rows);
}

// round 2
// speedup vs baseline: 1.5262x; 1.5262x over previous
#include <cuda_runtime.h>

#define NT 1024

// ---- shared-memory layout (float offsets, all multiples of 4 for float4) ----
#define OFF_E0 0        // ext buf L=16384 : 16384+38 -> 16424
#define OFF_E1 16424    // ext buf L=8199  : 8199+38  -> 8240
#define OFF_E2 24664    // ext buf L=4107  : 4107+38  -> 4148
#define OFF_E3 28812    // ext buf L=2061  : 2061+38  -> 2100
#define OFF_A4 30912    // approx lvl4 1038 (+pad)    -> 1044
#define OFF_D1 31956    // 8199 (+pad) -> 8204
#define OFF_D2 40160    // 4107 (+pad) -> 4112
#define OFF_D3 44272    // 2061 (+pad) -> 2068
#define OFF_D4 46340    // 1038 (+pad) -> 1044
#define OFF_HIST 47384  // 256 ints histogram + 2 scalars
#define SMEM_FLOATS (47384 + 260)
#define SMEM_BYTES  (SMEM_FLOATS * 4)

#define DECL_H const float H[16] = { \
    0.05441584224308161f,  0.3128715909144659f,   0.6756307362980128f,    0.5853546836548691f, \
   -0.015829105256023893f,-0.2840155429624281f,   0.00047248457399797254f,0.128747426620186f, \
   -0.01736930100202211f, -0.04408825393106472f,  0.013981027917015516f,  0.008746094047015655f, \
   -0.00487035299301066f, -0.0003917403729959771f,0.0006754494059985568f,-0.00011747678400228192f }

// Forward DWT one level.
// Ein: shifted symmetric extension, E[m] = a[m-14] (interior m in [14, L+13],
// borders prefilled). Writes ca into caout (+14 offset if ext_out, plus border
// refill), cd into D. Output length Lc = (L+15)>>1.
__device__ __forceinline__ void fwd_level(const float* __restrict__ Ein,
                                          float* __restrict__ caout,
                                          float* __restrict__ D,
                                          int L, int ext_out, int tid)
{
    DECL_H;
    const int Lc    = (L + 15) >> 1;
    const int npair = (Lc + 1) >> 1;
    const int caoff = ext_out ? 14 : 0;
    for (int u = tid; u < npair; u += NT) {
        const float4* p = (const float4*)(Ein + 4 * u);
        float4 q0 = p[0], q1 = p[1], q2 = p[2], q3 = p[3], q4 = p[4];
        float e[20] = { q0.x,q0.y,q0.z,q0.w, q1.x,q1.y,q1.z,q1.w,
                        q2.x,q2.y,q2.z,q2.w, q3.x,q3.y,q3.z,q3.w,
                        q4.x,q4.y,q4.z,q4.w };
        float ca0 = 0.f, cd0 = 0.f, ca1 = 0.f, cd1 = 0.f;
        #pragma unroll
        for (int i = 0; i < 16; i++) {
            const float g = ((i & 1) ? -H[15 - i] : H[15 - i]);   // (-1)^i * H[15-i]
            ca0 += H[i] * e[i];     cd0 += g * e[i];
            ca1 += H[i] * e[i + 2]; cd1 += g * e[i + 2];
        }
        caout[caoff + 2 * u] = ca0;
        D[2 * u] = cd0;
        if (2 * u + 1 < Lc) { caout[caoff + 2 * u + 1] = ca1; D[2 * u + 1] = cd1; }
    }
    __syncthreads();
    if (ext_out) {
        // rebuild symmetric borders of the freshly written ext buffer
        if (tid < 14)      caout[tid] = caout[27 - tid];
        else if (tid < 30) { int m = Lc + tid; caout[m] = caout[2 * Lc + 27 - m]; }
        __syncthreads();
    }
}

// Inverse DWT one level into shared memory. No boundary handling needed
// (slice [F-2:2n] keeps only full-support outputs). 8 outputs per thread-iter.
__device__ __forceinline__ void inv_level(const float* __restrict__ ca,
                                          const float* __restrict__ cd,
                                          float* __restrict__ outsh,
                                          int n_out, int tid)
{
    DECL_H;
    const int nu = (n_out + 7) >> 3;
    for (int u = tid; u < nu; u += NT) {
        const float4* pa = (const float4*)(ca + 4 * u);
        const float4* pc = (const float4*)(cd + 4 * u);
        float4 a0 = pa[0], a1 = pa[1], a2 = pa[2];
        float4 c0 = pc[0], c1 = pc[1], c2 = pc[2];
        float A[12] = { a0.x,a0.y,a0.z,a0.w, a1.x,a1.y,a1.z,a1.w, a2.x,a2.y,a2.z,a2.w };
        float C[12] = { c0.x,c0.y,c0.z,c0.w, c1.x,c1.y,c1.z,c1.w, c2.x,c2.y,c2.z,c2.w };
        float r[8];
        #pragma unroll
        for (int j = 0; j < 4; j++) {
            float re = 0.f, ro = 0.f;
            #pragma unroll
            for (int i = 0; i < 8; i++) {
                re += H[14 - 2 * i] * A[j + i] + H[2 * i + 1] * C[j + i];
                ro += H[15 - 2 * i] * A[j + i] - H[2 * i]     * C[j + i];
            }
            r[2 * j]     = re;
            r[2 * j + 1] = ro;
        }
        const int base = 8 * u;
        #pragma unroll
        for (int j = 0; j < 8; j++)
            if (base + j < n_out) outsh[base + j] = r[j];
    }
    __syncthreads();
}

// Final inverse level: n_out = 16384 exactly, write straight to gmem (float4).
__device__ __forceinline__ void inv_final(const float* __restrict__ ca,
                                          const float* __restrict__ cd,
                                          float* __restrict__ gout, int tid)
{
    DECL_H;
    for (int u = tid; u < 2048; u += NT) {
        const float4* pa = (const float4*)(ca + 4 * u);
        const float4* pc = (const float4*)(cd + 4 * u);
        float4 a0 = pa[0], a1 = pa[1], a2 = pa[2];
        float4 c0 = pc[0], c1 = pc[1], c2 = pc[2];
        float A[12] = { a0.x,a0.y,a0.z,a0.w, a1.x,a1.y,a1.z,a1.w, a2.x,a2.y,a2.z,a2.w };
        float C[12] = { c0.x,c0.y,c0.z,c0.w, c1.x,c1.y,c1.z,c1.w, c2.x,c2.y,c2.z,c2.w };
        float r[8];
        #pragma unroll
        for (int j = 0; j < 4; j++) {
            float re = 0.f, ro = 0.f;
            #pragma unroll
            for (int i = 0; i < 8; i++) {
                re += H[14 - 2 * i] * A[j + i] + H[2 * i + 1] * C[j + i];
                ro += H[15 - 2 * i] * A[j + i] - H[2 * i]     * C[j + i];
            }
            r[2 * j]     = re;
            r[2 * j + 1] = ro;
        }
        float4* po = (float4*)(gout + 8 * u);
        po[0] = make_float4(r[0], r[1], r[2], r[3]);
        po[1] = make_float4(r[4], r[5], r[6], r[7]);
    }
}

__global__ void __launch_bounds__(NT, 1)
wden_kernel(const float* __restrict__ x, float* __restrict__ out, int rows)
{
    extern __shared__ float sm[];
    const int tid = threadIdx.x;
    const int row = blockIdx.x;
    if (row >= rows) return;

    float* E0 = sm + OFF_E0;  float* E1 = sm + OFF_E1;
    float* E2 = sm + OFF_E2;  float* E3 = sm + OFF_E3;
    float* A4 = sm + OFF_A4;
    float* D1 = sm + OFF_D1;  float* D2 = sm + OFF_D2;
    float* D3 = sm + OFF_D3;  float* D4 = sm + OFF_D4;
    int*   hist = (int*)(sm + OFF_HIST);

    const float* xr = x + (size_t)row * 16384;

    // load row into E0 interior (E0[14 + i] = x[i]) + symmetric borders
    for (int i = tid; i < 4096; i += NT) {
        float4 v = ((const float4*)xr)[i];
        *(float2*)(E0 + 14 + 4 * i) = make_float2(v.x, v.y);
        *(float2*)(E0 + 16 + 4 * i) = make_float2(v.z, v.w);
    }
    if (tid < 14)      E0[tid] = xr[13 - tid];
    else if (tid < 30) { int m = 16384 + tid; E0[m] = xr[32781 - m]; }
    __syncthreads();

    // forward DWT: 16384 -> 8199 -> 4107 -> 2061 -> 1038
    fwd_level(E0, E1, D1, 16384, 1, tid);
    fwd_level(E1, E2, D2, 8199,  1, tid);
    fwd_level(E2, E3, D3, 4107,  1, tid);
    fwd_level(E3, A4, D4, 2061,  0, tid);

    // median(|D1|): rank 4099 of 8199, 4-round MSB radix select on float bits.
    // Histogram scan is done by warp 0 with a shuffle prefix-sum (no serial loop).
    unsigned pref = 0; int kk = 4099;
    for (int round = 0; round < 4; round++) {
        const int shift = 24 - 8 * round;
        const unsigned hmask = (round == 0) ? 0u : (0xFFFFFFFFu << (shift + 8));
        for (int i = tid; i < 256; i += NT) hist[i] = 0;
        __syncthreads();
        for (int i = tid; i < 8199; i += NT) {
            unsigned b = __float_as_uint(fabsf(D1[i]));
            if ((b & hmask) == pref) atomicAdd(&hist[(b >> shift) & 255], 1);
        }
        __syncthreads();
        if (tid < 32) {
            int s[8]; int tot = 0;
            #pragma unroll
            for (int j = 0; j < 8; j++) { s[j] = hist[tid * 8 + j]; tot += s[j]; }
            int run = tot;
            #pragma unroll
            for (int off = 1; off < 32; off <<= 1) {
                int n = __shfl_up_sync(0xFFFFFFFFu, run, off);
                if (tid >= (unsigned)off) run += n;
            }
            int excl = run - tot;
            if (kk >= excl && kk < excl + tot) {
                int acc = excl;
                #pragma unroll
                for (int j = 0; j < 8; j++) {
                    if (acc + s[j] > kk) {
                        hist[256] = (int)(pref | ((unsigned)(tid * 8 + j) << shift));
                        hist[257] = kk - acc;
                        break;
                    }
                    acc += s[j];
                }
            }
        }
        __syncthreads();
        pref = (unsigned)hist[256];
        kk   = hist[257];
    }
    const float med = __uint_as_float(pref);
    const float thr = (med / 0.6745f) * 4.4054649f;   // sqrt(2*ln(16384))

    // soft-threshold all detail bands in place
    for (int i = tid; i < 8199; i += NT) { float v = D1[i]; float a = fabsf(v) - thr; D1[i] = a > 0.f ? copysignf(a, v) : 0.f; }
    for (int i = tid; i < 4107; i += NT) { float v = D2[i]; float a = fabsf(v) - thr; D2[i] = a > 0.f ? copysignf(a, v) : 0.f; }
    for (int i = tid; i < 2061; i += NT) { float v = D3[i]; float a = fabsf(v) - thr; D3[i] = a > 0.f ? copysignf(a, v) : 0.f; }
    for (int i = tid; i < 1038; i += NT) { float v = D4[i]; float a = fabsf(v) - thr; D4[i] = a > 0.f ? copysignf(a, v) : 0.f; }
    __syncthreads();

    // inverse DWT: 1038 -> 2061 -> 4107 -> 8199 -> 16384 (reuse dead ext bufs)
    inv_level(A4, D4, E3, 2061, tid);
    inv_level(E3, D3, E2, 4107, tid);
    inv_level(E2, D2, E1, 8199, tid);
    inv_final(E1, D1, out + (size_t)row * 16384, tid);
}

extern "C" void kernel_launch(void* const* d_in, const int* in_sizes, int n_in,
                              void* d_out, int out_size)
{
    const float* x = (const float*)d_in[0];
    float* out = (float*)d_out;
    const int rows = in_sizes[0] / 16384;   // 128*16 = 2048
    cudaFuncSetAttribute(wden_kernel, cudaFuncAttributeMaxDynamicSharedMemorySize, SMEM_BYTES);
    wden_kernel<<<rows, NT, SMEM_BYTES>>>(x, out, rows);
}

// round 3
// speedup vs baseline: 2.0161x; 1.3210x over previous
#include <cuda_runtime.h>

#define NT 512

// ---- shared-memory layout (float offsets), aggressively aliased ----
// Region A [0, 8240): E1 (fwd1 out / fwd2 in), then after fwd2 is dead:
//     E3/R3 at A+0    (2112)   fwd3 out / fwd4 in / inv4 out / inv3 in
//     D3    at A+2112 (2080)
//     A4    at A+4192 (1056)
//     D4    at A+5248 (1056)
//     HIST  at A+6304 (260 ints)
//   finally R1 (inv2 out, 8199) overwrites all of region A.
// Region B [8240, 16448): D1 (8199 + pad)
// Region C [16448, 20608): E2 (4107+38 ext) then R2 (inv3 out)
// Region D [20608, 24720): D2 (4107 + pad)
#define OFF_E1   0
#define OFF_E3   0
#define OFF_D3   2112
#define OFF_A4   4192
#define OFF_D4   5248
#define OFF_HIST 6304
#define OFF_D1   8240
#define OFF_E2   16448
#define OFF_D2   20608
#define SMEM_FLOATS 24720
#define SMEM_BYTES  (SMEM_FLOATS * 4)

#define DECL_H const float H[16] = { \
    0.05441584224308161f,  0.3128715909144659f,   0.6756307362980128f,    0.5853546836548691f, \
   -0.015829105256023893f,-0.2840155429624281f,   0.00047248457399797254f,0.128747426620186f, \
   -0.01736930100202211f, -0.04408825393106472f,  0.013981027917015516f,  0.008746094047015655f, \
   -0.00487035299301066f, -0.0003917403729959771f,0.0006754494059985568f,-0.00011747678400228192f }

// symmetric-extension index map for the level-1 input row (L=16384):
// E[m] = x[sym(m)], interior m in [14, 16397]
__device__ __forceinline__ int symidx(int m) {
    if (m < 14)     return 13 - m;
    if (m > 16397)  return 32781 - m;
    return m - 14;
}

// Level-1 forward straight from gmem. Groups of 4 outputs per thread-iter.
// Group v covers w = 4v..4v+3, needing E[8v .. 8v+21] = x[8v-14 .. 8v+7];
// interior groups load the aligned float4 window [8v-16, 8v+8).
__device__ void fwd1_gmem(const float* __restrict__ xr,
                          float* __restrict__ E1out,
                          float* __restrict__ D1, int tid)
{
    DECL_H;
    for (int v = tid; v < 2050; v += NT) {
        float e[24];                       // e[j] = E[8v - 2 + j]
        if (v >= 2 && v <= 2047) {
            const float4* px = (const float4*)(xr + 8 * v - 16);
            #pragma unroll
            for (int q = 0; q < 6; q++) {
                float4 t = px[q];
                e[4*q] = t.x; e[4*q+1] = t.y; e[4*q+2] = t.z; e[4*q+3] = t.w;
            }
        } else {
            #pragma unroll
            for (int j = 0; j < 24; j++)
                e[j] = xr[symidx(8 * v - 2 + j)];
        }
        #pragma unroll
        for (int k = 0; k < 4; k++) {
            float ca = 0.f, cd = 0.f;
            #pragma unroll
            for (int i = 0; i < 16; i++) {
                const float g = ((i & 1) ? -H[15 - i] : H[15 - i]);
                ca += H[i] * e[2*k + i + 2];
                cd += g    * e[2*k + i + 2];
            }
            const int w = 4 * v + k;
            if (w < 8199) { E1out[14 + w] = ca; D1[w] = cd; }
        }
    }
    __syncthreads();
    if (tid < 14)      E1out[tid] = E1out[27 - tid];
    else if (tid < 30) { int m = 8199 + tid; E1out[m] = E1out[16425 - m]; }
    __syncthreads();
}

// Forward DWT one level from an ext smem buffer (E[m]=a[m-14], borders filled).
__device__ __forceinline__ void fwd_level(const float* __restrict__ Ein,
                                          float* __restrict__ caout,
                                          float* __restrict__ D,
                                          int L, int ext_out, int tid)
{
    DECL_H;
    const int Lc    = (L + 15) >> 1;
    const int npair = (Lc + 1) >> 1;
    const int caoff = ext_out ? 14 : 0;
    for (int u = tid; u < npair; u += NT) {
        const float4* p = (const float4*)(Ein + 4 * u);
        float4 q0 = p[0], q1 = p[1], q2 = p[2], q3 = p[3], q4 = p[4];
        float e[20] = { q0.x,q0.y,q0.z,q0.w, q1.x,q1.y,q1.z,q1.w,
                        q2.x,q2.y,q2.z,q2.w, q3.x,q3.y,q3.z,q3.w,
                        q4.x,q4.y,q4.z,q4.w };
        float ca0 = 0.f, cd0 = 0.f, ca1 = 0.f, cd1 = 0.f;
        #pragma unroll
        for (int i = 0; i < 16; i++) {
            const float g = ((i & 1) ? -H[15 - i] : H[15 - i]);
            ca0 += H[i] * e[i];     cd0 += g * e[i];
            ca1 += H[i] * e[i + 2]; cd1 += g * e[i + 2];
        }
        caout[caoff + 2 * u] = ca0;
        D[2 * u] = cd0;
        if (2 * u + 1 < Lc) { caout[caoff + 2 * u + 1] = ca1; D[2 * u + 1] = cd1; }
    }
    __syncthreads();
    if (ext_out) {
        if (tid < 14)      caout[tid] = caout[27 - tid];
        else if (tid < 30) { int m = Lc + tid; caout[m] = caout[2 * Lc + 27 - m]; }
        __syncthreads();
    }
}

// Inverse DWT one level into shared memory (full-support outputs only).
__device__ __forceinline__ void inv_level(const float* __restrict__ ca,
                                          const float* __restrict__ cd,
                                          float* __restrict__ outsh,
                                          int n_out, int tid)
{
    DECL_H;
    const int nu = (n_out + 7) >> 3;
    for (int u = tid; u < nu; u += NT) {
        const float4* pa = (const float4*)(ca + 4 * u);
        const float4* pc = (const float4*)(cd + 4 * u);
        float4 a0 = pa[0], a1 = pa[1], a2 = pa[2];
        float4 c0 = pc[0], c1 = pc[1], c2 = pc[2];
        float A[12] = { a0.x,a0.y,a0.z,a0.w, a1.x,a1.y,a1.z,a1.w, a2.x,a2.y,a2.z,a2.w };
        float C[12] = { c0.x,c0.y,c0.z,c0.w, c1.x,c1.y,c1.z,c1.w, c2.x,c2.y,c2.z,c2.w };
        float r[8];
        #pragma unroll
        for (int j = 0; j < 4; j++) {
            float re = 0.f, ro = 0.f;
            #pragma unroll
            for (int i = 0; i < 8; i++) {
                re += H[14 - 2 * i] * A[j + i] + H[2 * i + 1] * C[j + i];
                ro += H[15 - 2 * i] * A[j + i] - H[2 * i]     * C[j + i];
            }
            r[2 * j]     = re;
            r[2 * j + 1] = ro;
        }
        const int base = 8 * u;
        #pragma unroll
        for (int j = 0; j < 8; j++)
            if (base + j < n_out) outsh[base + j] = r[j];
    }
    __syncthreads();
}

// Final inverse level: n_out = 16384 exactly, write straight to gmem (float4).
__device__ __forceinline__ void inv_final(const float* __restrict__ ca,
                                          const float* __restrict__ cd,
                                          float* __restrict__ gout, int tid)
{
    DECL_H;
    for (int u = tid; u < 2048; u += NT) {
        const float4* pa = (const float4*)(ca + 4 * u);
        const float4* pc = (const float4*)(cd + 4 * u);
        float4 a0 = pa[0], a1 = pa[1], a2 = pa[2];
        float4 c0 = pc[0], c1 = pc[1], c2 = pc[2];
        float A[12] = { a0.x,a0.y,a0.z,a0.w, a1.x,a1.y,a1.z,a1.w, a2.x,a2.y,a2.z,a2.w };
        float C[12] = { c0.x,c0.y,c0.z,c0.w, c1.x,c1.y,c1.z,c1.w, c2.x,c2.y,c2.z,c2.w };
        float r[8];
        #pragma unroll
        for (int j = 0; j < 4; j++) {
            float re = 0.f, ro = 0.f;
            #pragma unroll
            for (int i = 0; i < 8; i++) {
                re += H[14 - 2 * i] * A[j + i] + H[2 * i + 1] * C[j + i];
                ro += H[15 - 2 * i] * A[j + i] - H[2 * i]     * C[j + i];
            }
            r[2 * j]     = re;
            r[2 * j + 1] = ro;
        }
        float4* po = (float4*)(gout + 8 * u);
        po[0] = make_float4(r[0], r[1], r[2], r[3]);
        po[1] = make_float4(r[4], r[5], r[6], r[7]);
    }
}

__global__ void __launch_bounds__(NT, 2)
wden_kernel(const float* __restrict__ x, float* __restrict__ out, int rows)
{
    extern __shared__ float sm[];
    const int tid = threadIdx.x;
    const int row = blockIdx.x;
    if (row >= rows) return;

    float* E1 = sm + OFF_E1;   // region A
    float* E3 = sm + OFF_E3;   // alias of A (E1 dead after fwd2)
    float* D3 = sm + OFF_D3;
    float* A4 = sm + OFF_A4;
    float* D4 = sm + OFF_D4;
    int*   hist = (int*)(sm + OFF_HIST);
    float* D1 = sm + OFF_D1;
    float* E2 = sm + OFF_E2;   // later R2
    float* D2 = sm + OFF_D2;

    const float* xr = x + (size_t)row * 16384;

    // forward DWT: 16384 -> 8199 -> 4107 -> 2061 -> 1038
    fwd1_gmem(xr, E1, D1, tid);                 // reads gmem, writes E1, D1
    fwd_level(E1, E2, D2, 8199,  1, tid);       // E1 dead after this
    fwd_level(E2, E3, D3, 4107,  1, tid);       // E2 dead after this
    fwd_level(E3, A4, D4, 2061,  0, tid);

    // median(|D1|): rank 4099 of 8199, 4-round MSB radix select on float bits.
    unsigned pref = 0; int kk = 4099;
    for (int round = 0; round < 4; round++) {
        const int shift = 24 - 8 * round;
        const unsigned hmask = (round == 0) ? 0u : (0xFFFFFFFFu << (shift + 8));
        for (int i = tid; i < 256; i += NT) hist[i] = 0;
        __syncthreads();
        for (int i = tid; i < 8199; i += NT) {
            unsigned b = __float_as_uint(fabsf(D1[i]));
            if ((b & hmask) == pref) atomicAdd(&hist[(b >> shift) & 255], 1);
        }
        __syncthreads();
        if (tid < 32) {
            int s[8]; int tot = 0;
            #pragma unroll
            for (int j = 0; j < 8; j++) { s[j] = hist[tid * 8 + j]; tot += s[j]; }
            int run = tot;
            #pragma unroll
            for (int off = 1; off < 32; off <<= 1) {
                int n = __shfl_up_sync(0xFFFFFFFFu, run, off);
                if (tid >= (unsigned)off) run += n;
            }
            int excl = run - tot;
            if (kk >= excl && kk < excl + tot) {
                int acc = excl;
                #pragma unroll
                for (int j = 0; j < 8; j++) {
                    if (acc + s[j] > kk) {
                        hist[256] = (int)(pref | ((unsigned)(tid * 8 + j) << shift));
                        hist[257] = kk - acc;
                        break;
                    }
                    acc += s[j];
                }
            }
        }
        __syncthreads();
        pref = (unsigned)hist[256];
        kk   = hist[257];
    }
    const float med = __uint_as_float(pref);
    const float thr = (med / 0.6745f) * 4.4054649f;   // sqrt(2*ln(16384))

    // soft-threshold all detail bands in place
    for (int i = tid; i < 8199; i += NT) { float v = D1[i]; float a = fabsf(v) - thr; D1[i] = a > 0.f ? copysignf(a, v) : 0.f; }
    for (int i = tid; i < 4107; i += NT) { float v = D2[i]; float a = fabsf(v) - thr; D2[i] = a > 0.f ? copysignf(a, v) : 0.f; }
    for (int i = tid; i < 2061; i += NT) { float v = D3[i]; float a = fabsf(v) - thr; D3[i] = a > 0.f ? copysignf(a, v) : 0.f; }
    for (int i = tid; i < 1038; i += NT) { float v = D4[i]; float a = fabsf(v) - thr; D4[i] = a > 0.f ? copysignf(a, v) : 0.f; }
    __syncthreads();

    // inverse DWT, reusing dead regions:
    inv_level(A4, D4, E3, 2061, tid);   // R3 -> E3 slot (A+0); reads A+4192.. : no overlap
    inv_level(E3, D3, E2, 4107, tid);   // R2 -> E2 slot (region C)
    inv_level(E2, D2, E1, 8199, tid);   // R1 -> region A (E3/D3/A4/D4/hist all dead)
    inv_final(E1, D1, out + (size_t)row * 16384, tid);
}

extern "C" void kernel_launch(void* const* d_in, const int* in_sizes, int n_in,
                              void* d_out, int out_size)
{
    const float* x = (const float*)d_in[0];
    float* out = (float*)d_out;
    const int rows = in_sizes[0] / 16384;   // 128*16 = 2048
    cudaFuncSetAttribute(wden_kernel, cudaFuncAttributeMaxDynamicSharedMemorySize, SMEM_BYTES);
    wden_kernel<<<rows, NT, SMEM_BYTES>>>(x, out, rows);
}

// round 4
// speedup vs baseline: 2.1098x; 1.0465x over previous
#include <cuda_runtime.h>

#define NT 512

// ---- shared-memory layout (float offsets), aggressively aliased ----
// Region A [0, 8240): E1 (fwd1 out / fwd2 in), then after fwd2 is dead:
//     E3/R3 at A+0    (2112)   fwd3 out / fwd4 in / inv4 out / inv3 in
//     D3    at A+2112 (2080)
//     A4    at A+4192 (1056)
//     D4    at A+5248 (1056)
//     HIST  at A+6304 (260 ints)
//   finally R1 (inv2 out, 8199) overwrites all of region A.
// Region B [8240, 16448): D1 (8199 + pad)
// Region C [16448, 20608): E2 (4107+38 ext) then R2 (inv3 out)
// Region D [20608, 24720): D2 (4107 + pad)
#define OFF_E1   0
#define OFF_E3   0
#define OFF_D3   2112
#define OFF_A4   4192
#define OFF_D4   5248
#define OFF_HIST 6304
#define OFF_D1   8240
#define OFF_E2   16448
#define OFF_D2   20608
#define SMEM_FLOATS 24720
#define SMEM_BYTES  (SMEM_FLOATS * 4)

#define DECL_H const float H[16] = { \
    0.05441584224308161f,  0.3128715909144659f,   0.6756307362980128f,    0.5853546836548691f, \
   -0.015829105256023893f,-0.2840155429624281f,   0.00047248457399797254f,0.128747426620186f, \
   -0.01736930100202211f, -0.04408825393106472f,  0.013981027917015516f,  0.008746094047015655f, \
   -0.00487035299301066f, -0.0003917403729959771f,0.0006754494059985568f,-0.00011747678400228192f }

// symmetric-extension index map for the level-1 input row (L=16384):
// E[m] = x[sym(m)], interior m in [14, 16397]
__device__ __forceinline__ int symidx(int m) {
    if (m < 14)     return 13 - m;
    if (m > 16397)  return 32781 - m;
    return m - 14;
}

__device__ __forceinline__ float softthr(float v, float thr) {
    float a = fabsf(v) - thr;
    return a > 0.f ? copysignf(a, v) : 0.f;
}

// Level-1 forward straight from gmem. 4 outputs per thread-iter.
// Group v covers w = 4v..4v+3, needing E[8v .. 8v+21] = x[8v-14 .. 8v+7];
// interior groups load the aligned float4 window [8v-16, 8v+8).
__device__ void fwd1_gmem(const float* __restrict__ xr,
                          float* __restrict__ E1out,
                          float* __restrict__ D1, int tid)
{
    DECL_H;
    for (int v = tid; v < 2050; v += NT) {
        float e[24];                       // e[j] = E[8v - 2 + j]
        if (v >= 2 && v <= 2047) {
            const float4* px = (const float4*)(xr + 8 * v - 16);
            #pragma unroll
            for (int q = 0; q < 6; q++) {
                float4 t = px[q];
                e[4*q] = t.x; e[4*q+1] = t.y; e[4*q+2] = t.z; e[4*q+3] = t.w;
            }
        } else {
            #pragma unroll
            for (int j = 0; j < 24; j++)
                e[j] = xr[symidx(8 * v - 2 + j)];
        }
        float ca[4], cd[4];
        #pragma unroll
        for (int k = 0; k < 4; k++) {
            float a = 0.f, d = 0.f;
            #pragma unroll
            for (int i = 0; i < 16; i++) {
                const float g = ((i & 1) ? -H[15 - i] : H[15 - i]);
                a += H[i] * e[2*k + i + 2];
                d += g    * e[2*k + i + 2];
            }
            ca[k] = a; cd[k] = d;
        }
        const int w0 = 4 * v;
        if (w0 + 4 <= 8199) {
            *(float2*)(E1out + 14 + w0)     = make_float2(ca[0], ca[1]);
            *(float2*)(E1out + 14 + w0 + 2) = make_float2(ca[2], ca[3]);
            *(float4*)(D1 + w0) = make_float4(cd[0], cd[1], cd[2], cd[3]);
        } else {
            #pragma unroll
            for (int k = 0; k < 4; k++)
                if (w0 + k < 8199) { E1out[14 + w0 + k] = ca[k]; D1[w0 + k] = cd[k]; }
        }
    }
    __syncthreads();
    if (tid < 14)      E1out[tid] = E1out[27 - tid];
    else if (tid < 30) { int m = 8199 + tid; E1out[m] = E1out[16425 - m]; }
    __syncthreads();
}

// Forward DWT one level from an ext smem buffer (E[m]=a[m-14], borders filled).
// 4 outputs per thread-iter: w=4u..4u+3 needs E[8u..8u+22] -> 6 aligned float4.
__device__ __forceinline__ void fwd_level(const float* __restrict__ Ein,
                                          float* __restrict__ caout,
                                          float* __restrict__ D,
                                          int L, int ext_out, int tid)
{
    DECL_H;
    const int Lc   = (L + 15) >> 1;
    const int nblk = (Lc + 3) >> 2;
    const int caoff = ext_out ? 14 : 0;
    for (int u = tid; u < nblk; u += NT) {
        const float4* p = (const float4*)(Ein + 8 * u);
        float e[24];
        #pragma unroll
        for (int q = 0; q < 6; q++) {
            float4 t = p[q];
            e[4*q] = t.x; e[4*q+1] = t.y; e[4*q+2] = t.z; e[4*q+3] = t.w;
        }
        float ca[4], cd[4];
        #pragma unroll
        for (int k = 0; k < 4; k++) {
            float a = 0.f, d = 0.f;
            #pragma unroll
            for (int i = 0; i < 16; i++) {
                const float g = ((i & 1) ? -H[15 - i] : H[15 - i]);
                a += H[i] * e[2*k + i];
                d += g    * e[2*k + i];
            }
            ca[k] = a; cd[k] = d;
        }
        const int w0 = 4 * u;
        if (w0 + 4 <= Lc) {
            *(float2*)(caout + caoff + w0)     = make_float2(ca[0], ca[1]);
            *(float2*)(caout + caoff + w0 + 2) = make_float2(ca[2], ca[3]);
            *(float4*)(D + w0) = make_float4(cd[0], cd[1], cd[2], cd[3]);
        } else {
            #pragma unroll
            for (int k = 0; k < 4; k++)
                if (w0 + k < Lc) { caout[caoff + w0 + k] = ca[k]; D[w0 + k] = cd[k]; }
        }
    }
    __syncthreads();
    if (ext_out) {
        if (tid < 14)      caout[tid] = caout[27 - tid];
        else if (tid < 30) { int m = Lc + tid; caout[m] = caout[2 * Lc + 27 - m]; }
        __syncthreads();
    }
}

// Inverse DWT one level into shared memory (full-support outputs only).
// Soft-thresholding of the detail band is fused into the load.
__device__ __forceinline__ void inv_level(const float* __restrict__ ca,
                                          const float* __restrict__ cd,
                                          float* __restrict__ outsh,
                                          int n_out, float thr, int tid)
{
    DECL_H;
    const int nu = (n_out + 7) >> 3;
    for (int u = tid; u < nu; u += NT) {
        const float4* pa = (const float4*)(ca + 4 * u);
        const float4* pc = (const float4*)(cd + 4 * u);
        float4 a0 = pa[0], a1 = pa[1], a2 = pa[2];
        float4 c0 = pc[0], c1 = pc[1], c2 = pc[2];
        float A[12] = { a0.x,a0.y,a0.z,a0.w, a1.x,a1.y,a1.z,a1.w, a2.x,a2.y,a2.z,a2.w };
        float C[12] = { c0.x,c0.y,c0.z,c0.w, c1.x,c1.y,c1.z,c1.w, c2.x,c2.y,c2.z,c2.w };
        #pragma unroll
        for (int i = 0; i < 12; i++) C[i] = softthr(C[i], thr);
        float r[8];
        #pragma unroll
        for (int j = 0; j < 4; j++) {
            float re = 0.f, ro = 0.f;
            #pragma unroll
            for (int i = 0; i < 8; i++) {
                re += H[14 - 2 * i] * A[j + i] + H[2 * i + 1] * C[j + i];
                ro += H[15 - 2 * i] * A[j + i] - H[2 * i]     * C[j + i];
            }
            r[2 * j]     = re;
            r[2 * j + 1] = ro;
        }
        const int base = 8 * u;
        #pragma unroll
        for (int j = 0; j < 8; j++)
            if (base + j < n_out) outsh[base + j] = r[j];
    }
    __syncthreads();
}

// Final inverse level: n_out = 16384 exactly, write straight to gmem (float4).
__device__ __forceinline__ void inv_final(const float* __restrict__ ca,
                                          const float* __restrict__ cd,
                                          float* __restrict__ gout, float thr, int tid)
{
    DECL_H;
    for (int u = tid; u < 2048; u += NT) {
        const float4* pa = (const float4*)(ca + 4 * u);
        const float4* pc = (const float4*)(cd + 4 * u);
        float4 a0 = pa[0], a1 = pa[1], a2 = pa[2];
        float4 c0 = pc[0], c1 = pc[1], c2 = pc[2];
        float A[12] = { a0.x,a0.y,a0.z,a0.w, a1.x,a1.y,a1.z,a1.w, a2.x,a2.y,a2.z,a2.w };
        float C[12] = { c0.x,c0.y,c0.z,c0.w, c1.x,c1.y,c1.z,c1.w, c2.x,c2.y,c2.z,c2.w };
        #pragma unroll
        for (int i = 0; i < 12; i++) C[i] = softthr(C[i], thr);
        float r[8];
        #pragma unroll
        for (int j = 0; j < 4; j++) {
            float re = 0.f, ro = 0.f;
            #pragma unroll
            for (int i = 0; i < 8; i++) {
                re += H[14 - 2 * i] * A[j + i] + H[2 * i + 1] * C[j + i];
                ro += H[15 - 2 * i] * A[j + i] - H[2 * i]     * C[j + i];
            }
            r[2 * j]     = re;
            r[2 * j + 1] = ro;
        }
        float4* po = (float4*)(gout + 8 * u);
        po[0] = make_float4(r[0], r[1], r[2], r[3]);
        po[1] = make_float4(r[4], r[5], r[6], r[7]);
    }
}

__global__ void __launch_bounds__(NT, 2)
wden_kernel(const float* __restrict__ x, float* __restrict__ out, int rows)
{
    extern __shared__ float sm[];
    const int tid = threadIdx.x;
    const int row = blockIdx.x;
    if (row >= rows) return;

    float* E1 = sm + OFF_E1;   // region A
    float* E3 = sm + OFF_E3;   // alias of A (E1 dead after fwd2)
    float* D3 = sm + OFF_D3;
    float* A4 = sm + OFF_A4;
    float* D4 = sm + OFF_D4;
    int*   hist = (int*)(sm + OFF_HIST);
    float* D1 = sm + OFF_D1;
    float* E2 = sm + OFF_E2;   // later R2
    float* D2 = sm + OFF_D2;

    const float* xr = x + (size_t)row * 16384;

    // forward DWT: 16384 -> 8199 -> 4107 -> 2061 -> 1038
    fwd1_gmem(xr, E1, D1, tid);                 // reads gmem, writes E1, D1
    fwd_level(E1, E2, D2, 8199,  1, tid);       // E1 dead after this
    fwd_level(E2, E3, D3, 4107,  1, tid);       // E2 dead after this
    fwd_level(E3, A4, D4, 2061,  0, tid);

    // median(|D1|): rank 4099 of 8199, 4-round MSB radix select on float bits.
    unsigned pref = 0; int kk = 4099;
    for (int round = 0; round < 4; round++) {
        const int shift = 24 - 8 * round;
        const unsigned hmask = (round == 0) ? 0u : (0xFFFFFFFFu << (shift + 8));
        for (int i = tid; i < 256; i += NT) hist[i] = 0;
        __syncthreads();
        for (int i = tid; i < 8199; i += NT) {
            unsigned b = __float_as_uint(fabsf(D1[i]));
            if ((b & hmask) == pref) atomicAdd(&hist[(b >> shift) & 255], 1);
        }
        __syncthreads();
        if (tid < 32) {
            int s[8]; int tot = 0;
            #pragma unroll
            for (int j = 0; j < 8; j++) { s[j] = hist[tid * 8 + j]; tot += s[j]; }
            int run = tot;
            #pragma unroll
            for (int off = 1; off < 32; off <<= 1) {
                int n = __shfl_up_sync(0xFFFFFFFFu, run, off);
                if (tid >= (unsigned)off) run += n;
            }
            int excl = run - tot;
            if (kk >= excl && kk < excl + tot) {
                int acc = excl;
                #pragma unroll
                for (int j = 0; j < 8; j++) {
                    if (acc + s[j] > kk) {
                        hist[256] = (int)(pref | ((unsigned)(tid * 8 + j) << shift));
                        hist[257] = kk - acc;
                        break;
                    }
                    acc += s[j];
                }
            }
        }
        __syncthreads();
        pref = (unsigned)hist[256];
        kk   = hist[257];
    }
    const float med = __uint_as_float(pref);
    const float thr = (med / 0.6745f) * 4.4054649f;   // sqrt(2*ln(16384))
    __syncthreads();   // hist region may be overwritten by R1 below

    // inverse DWT with fused soft-thresholding, reusing dead regions:
    inv_level(A4, D4, E3, 2061, thr, tid);   // R3 -> E3 slot (A+0)
    inv_level(E3, D3, E2, 4107, thr, tid);   // R2 -> E2 slot (region C)
    inv_level(E2, D2, E1, 8199, thr, tid);   // R1 -> region A (hist dead)
    inv_final(E1, D1, out + (size_t)row * 16384, thr, tid);
}

extern "C" void kernel_launch(void* const* d_in, const int* in_sizes, int n_in,
                              void* d_out, int out_size)
{
    const float* x = (const float*)d_in[0];
    float* out = (float*)d_out;
    const int rows = in_sizes[0] / 16384;   // 128*16 = 2048
    cudaFuncSetAttribute(wden_kernel, cudaFuncAttributeMaxDynamicSharedMemorySize, SMEM_BYTES);
    wden_kernel<<<rows, NT, SMEM_BYTES>>>(x, out, rows);
}

// round 7
// speedup vs baseline: 2.3132x; 1.0964x over previous
#include <cuda_runtime.h>

#define NT 512
typedef unsigned long long ull;

// ---- shared-memory layout (float offsets), aggressively aliased ----
#define OFF_E1   0
#define OFF_E3   0
#define OFF_D3   2112
#define OFF_A4   4192
#define OFF_D4   5248
#define OFF_HIST 6304
#define OFF_D1   8240
#define OFF_E2   16448
#define OFF_D2   20608
#define SMEM_FLOATS 24720
#define SMEM_BYTES  (SMEM_FLOATS * 4)

static constexpr float Hc[16] = {
    0.05441584224308161f,  0.3128715909144659f,   0.6756307362980128f,    0.5853546836548691f,
   -0.015829105256023893f,-0.2840155429624281f,   0.00047248457399797254f,0.128747426620186f,
   -0.01736930100202211f, -0.04408825393106472f,  0.013981027917015516f,  0.008746094047015655f,
   -0.00487035299301066f, -0.0003917403729959771f,0.0006754494059985568f,-0.00011747678400228192f };

__host__ __device__ static constexpr ull pk2(float lo, float hi) {
    return (ull)__builtin_bit_cast(unsigned int, lo) |
           ((ull)__builtin_bit_cast(unsigned int, hi) << 32);
}

// fwd: ca taps pairs (H[2m],H[2m+1]); cd taps pairs (G[2m],G[2m+1]), G[i]=(-1)^i H[15-i]
#define DECL_FWD_COEF \
    const ull CA2[8] = { pk2(Hc[0],Hc[1]),  pk2(Hc[2],Hc[3]),  pk2(Hc[4],Hc[5]),  pk2(Hc[6],Hc[7]), \
                         pk2(Hc[8],Hc[9]),  pk2(Hc[10],Hc[11]),pk2(Hc[12],Hc[13]),pk2(Hc[14],Hc[15]) }; \
    const ull CD2[8] = { pk2(Hc[15],-Hc[14]),pk2(Hc[13],-Hc[12]),pk2(Hc[11],-Hc[10]),pk2(Hc[9],-Hc[8]), \
                         pk2(Hc[7],-Hc[6]),  pk2(Hc[5],-Hc[4]),  pk2(Hc[3],-Hc[2]),  pk2(Hc[1],-Hc[0]) }

// inv: (re,ro) acc; A coef pairs (H[14-2i],H[15-2i]); C coef pairs (H[2i+1],-H[2i])
#define DECL_INV_COEF \
    const ull CIA[8] = { pk2(Hc[14],Hc[15]), pk2(Hc[12],Hc[13]), pk2(Hc[10],Hc[11]), pk2(Hc[8],Hc[9]), \
                         pk2(Hc[6],Hc[7]),   pk2(Hc[4],Hc[5]),   pk2(Hc[2],Hc[3]),   pk2(Hc[0],Hc[1]) }; \
    const ull CIC[8] = { pk2(Hc[1],-Hc[0]),  pk2(Hc[3],-Hc[2]),  pk2(Hc[5],-Hc[4]),  pk2(Hc[7],-Hc[6]), \
                         pk2(Hc[9],-Hc[8]),  pk2(Hc[11],-Hc[10]),pk2(Hc[13],-Hc[12]),pk2(Hc[15],-Hc[14]) }

__device__ __forceinline__ void ff2(ull& a, ull v, ull c) {
    asm("fma.rn.f32x2 %0, %1, %2, %0;" : "+l"(a) : "l"(v), "l"(c));
}
__device__ __forceinline__ float hadd2(ull v) {
    float lo, hi;
    asm("mov.b64 {%0, %1}, %2;" : "=f"(lo), "=f"(hi) : "l"(v));
    return lo + hi;
}
__device__ __forceinline__ ull pkf(float lo, float hi) {
    ull r; asm("mov.b64 %0, {%1, %2};" : "=l"(r) : "f"(lo), "f"(hi)); return r;
}
__device__ __forceinline__ float2 upk2(ull v) {
    float2 r; asm("mov.b64 {%0, %1}, %2;" : "=f"(r.x), "=f"(r.y) : "l"(v)); return r;
}

// symmetric-extension index map for the level-1 input row (L=16384)
__device__ __forceinline__ int symidx(int m) {
    if (m < 14)     return 13 - m;
    if (m > 16397)  return 32781 - m;
    return m - 14;
}

// Level-1 forward straight from gmem, packed-f32x2 taps. 4 outputs/thread-iter.
__device__ void fwd1_gmem(const float* __restrict__ xr,
                          float* __restrict__ E1out,
                          float* __restrict__ D1, int tid)
{
    DECL_FWD_COEF;
    for (int v = tid; v < 2050; v += NT) {
        ull P[12];                          // P[p] = (E[8v-2+2p], E[8v-2+2p+1])
        if (v >= 2 && v <= 2047) {
            const double2* px = (const double2*)(xr + 8 * v - 16);
            #pragma unroll
            for (int q = 0; q < 6; q++) {
                double2 t = px[q];
                P[2*q]   = __double_as_longlong(t.x);
                P[2*q+1] = __double_as_longlong(t.y);
            }
        } else {
            float e[24];
            #pragma unroll
            for (int j = 0; j < 24; j++) e[j] = xr[symidx(8 * v - 2 + j)];
            #pragma unroll
            for (int p = 0; p < 12; p++) P[p] = pkf(e[2*p], e[2*p+1]);
        }
        float ca[4], cd[4];
        #pragma unroll
        for (int k = 0; k < 4; k++) {       // output w=4v+k uses e[2k+2 .. 2k+17]
            ull aa = 0, ad = 0;
            #pragma unroll
            for (int m = 0; m < 8; m++) { ff2(aa, P[k+1+m], CA2[m]); ff2(ad, P[k+1+m], CD2[m]); }
            ca[k] = hadd2(aa); cd[k] = hadd2(ad);
        }
        const int w0 = 4 * v;
        if (w0 + 4 <= 8199) {
            *(float2*)(E1out + 14 + w0)     = make_float2(ca[0], ca[1]);
            *(float2*)(E1out + 14 + w0 + 2) = make_float2(ca[2], ca[3]);
            *(float4*)(D1 + w0) = make_float4(cd[0], cd[1], cd[2], cd[3]);
        } else {
            #pragma unroll
            for (int k = 0; k < 4; k++)
                if (w0 + k < 8199) { E1out[14 + w0 + k] = ca[k]; D1[w0 + k] = cd[k]; }
        }
    }
    __syncthreads();
    if (tid < 14)      E1out[tid] = E1out[27 - tid];
    else if (tid < 30) { int m = 8199 + tid; E1out[m] = E1out[16425 - m]; }
    __syncthreads();
}

// Forward DWT one level from an ext smem buffer, packed taps. 4 outputs/iter.
__device__ __forceinline__ void fwd_level(const float* __restrict__ Ein,
                                          float* __restrict__ caout,
                                          float* __restrict__ D,
                                          int L, int ext_out, int tid)
{
    DECL_FWD_COEF;
    const int Lc   = (L + 15) >> 1;
    const int nblk = (Lc + 3) >> 2;
    const int caoff = ext_out ? 14 : 0;
    for (int u = tid; u < nblk; u += NT) {
        const double2* p = (const double2*)(Ein + 8 * u);
        ull P[12];
        #pragma unroll
        for (int q = 0; q < 6; q++) {
            double2 t = p[q];
            P[2*q]   = __double_as_longlong(t.x);
            P[2*q+1] = __double_as_longlong(t.y);
        }
        float ca[4], cd[4];
        #pragma unroll
        for (int k = 0; k < 4; k++) {       // output w=4u+k uses e[2k .. 2k+15]
            ull aa = 0, ad = 0;
            #pragma unroll
            for (int m = 0; m < 8; m++) { ff2(aa, P[k+m], CA2[m]); ff2(ad, P[k+m], CD2[m]); }
            ca[k] = hadd2(aa); cd[k] = hadd2(ad);
        }
        const int w0 = 4 * u;
        if (w0 + 4 <= Lc) {
            *(float2*)(caout + caoff + w0)     = make_float2(ca[0], ca[1]);
            *(float2*)(caout + caoff + w0 + 2) = make_float2(ca[2], ca[3]);
            *(float4*)(D + w0) = make_float4(cd[0], cd[1], cd[2], cd[3]);
        } else {
            #pragma unroll
            for (int k = 0; k < 4; k++)
                if (w0 + k < Lc) { caout[caoff + w0 + k] = ca[k]; D[w0 + k] = cd[k]; }
        }
    }
    __syncthreads();
    if (ext_out) {
        if (tid < 14)      caout[tid] = caout[27 - tid];
        else if (tid < 30) { int m = Lc + tid; caout[m] = caout[2 * Lc + 27 - m]; }
        __syncthreads();
    }
}

__device__ __forceinline__ float softthr(float v, float thr) {
    return copysignf(fmaxf(fabsf(v) - thr, 0.0f), v);
}

// Inverse DWT one level into smem; (re,ro) packed accumulator; fused threshold.
__device__ __forceinline__ void inv_level(const float* __restrict__ ca,
                                          const float* __restrict__ cd,
                                          float* __restrict__ outsh,
                                          int n_out, float thr, int tid)
{
    DECL_INV_COEF;
    const int nu = (n_out + 7) >> 3;
    for (int u = tid; u < nu; u += NT) {
        const float4* pa = (const float4*)(ca + 4 * u);
        const float4* pc = (const float4*)(cd + 4 * u);
        float4 a0 = pa[0], a1 = pa[1], a2 = pa[2];
        float4 c0 = pc[0], c1 = pc[1], c2 = pc[2];
        float A[12] = { a0.x,a0.y,a0.z,a0.w, a1.x,a1.y,a1.z,a1.w, a2.x,a2.y,a2.z,a2.w };
        float C[12] = { c0.x,c0.y,c0.z,c0.w, c1.x,c1.y,c1.z,c1.w, c2.x,c2.y,c2.z,c2.w };
        ull Ad[12], Cd[12];
        #pragma unroll
        for (int m = 0; m < 12; m++) {
            Ad[m] = pkf(A[m], A[m]);
            float t = softthr(C[m], thr);
            Cd[m] = pkf(t, t);
        }
        float r[8];
        #pragma unroll
        for (int j = 0; j < 4; j++) {
            ull acc = 0;
            #pragma unroll
            for (int i = 0; i < 8; i++) { ff2(acc, Ad[j+i], CIA[i]); ff2(acc, Cd[j+i], CIC[i]); }
            float2 t = upk2(acc);
            r[2*j] = t.x; r[2*j+1] = t.y;
        }
        const int base = 8 * u;
        if (base + 8 <= n_out) {
            *(float4*)(outsh + base)     = make_float4(r[0], r[1], r[2], r[3]);
            *(float4*)(outsh + base + 4) = make_float4(r[4], r[5], r[6], r[7]);
        } else {
            #pragma unroll
            for (int j = 0; j < 8; j++)
                if (base + j < n_out) outsh[base + j] = r[j];
        }
    }
    __syncthreads();
}

// Final inverse level: n_out = 16384, writes straight to gmem.
__device__ __forceinline__ void inv_final(const float* __restrict__ ca,
                                          const float* __restrict__ cd,
                                          float* __restrict__ gout, float thr, int tid)
{
    DECL_INV_COEF;
    for (int u = tid; u < 2048; u += NT) {
        const float4* pa = (const float4*)(ca + 4 * u);
        const float4* pc = (const float4*)(cd + 4 * u);
        float4 a0 = pa[0], a1 = pa[1], a2 = pa[2];
        float4 c0 = pc[0], c1 = pc[1], c2 = pc[2];
        float A[12] = { a0.x,a0.y,a0.z,a0.w, a1.x,a1.y,a1.z,a1.w, a2.x,a2.y,a2.z,a2.w };
        float C[12] = { c0.x,c0.y,c0.z,c0.w, c1.x,c1.y,c1.z,c1.w, c2.x,c2.y,c2.z,c2.w };
        ull Ad[12], Cd[12];
        #pragma unroll
        for (int m = 0; m < 12; m++) {
            Ad[m] = pkf(A[m], A[m]);
            float t = softthr(C[m], thr);
            Cd[m] = pkf(t, t);
        }
        float r[8];
        #pragma unroll
        for (int j = 0; j < 4; j++) {
            ull acc = 0;
            #pragma unroll
            for (int i = 0; i < 8; i++) { ff2(acc, Ad[j+i], CIA[i]); ff2(acc, Cd[j+i], CIC[i]); }
            float2 t = upk2(acc);
            r[2*j] = t.x; r[2*j+1] = t.y;
        }
        float4* po = (float4*)(gout + 8 * u);
        po[0] = make_float4(r[0], r[1], r[2], r[3]);
        po[1] = make_float4(r[4], r[5], r[6], r[7]);
    }
}

__global__ void __launch_bounds__(NT, 2)
wden_kernel(const float* __restrict__ x, float* __restrict__ out, int rows)
{
    extern __shared__ float sm[];
    const int tid = threadIdx.x;
    const int row = blockIdx.x;
    if (row >= rows) return;

    float* E1 = sm + OFF_E1;
    float* E3 = sm + OFF_E3;
    float* D3 = sm + OFF_D3;
    float* A4 = sm + OFF_A4;
    float* D4 = sm + OFF_D4;
    int*   hist = (int*)(sm + OFF_HIST);
    float* D1 = sm + OFF_D1;
    float* E2 = sm + OFF_E2;
    float* D2 = sm + OFF_D2;

    const float* xr = x + (size_t)row * 16384;

    // forward DWT: 16384 -> 8199 -> 4107 -> 2061 -> 1038
    fwd1_gmem(xr, E1, D1, tid);
    fwd_level(E1, E2, D2, 8199,  1, tid);
    fwd_level(E2, E3, D3, 4107,  1, tid);
    fwd_level(E3, A4, D4, 2061,  0, tid);

    // median(|D1|): rank 4099 of 8199, 4-round MSB radix select on float bits.
    unsigned pref = 0; int kk = 4099;
    for (int round = 0; round < 4; round++) {
        const int shift = 24 - 8 * round;
        const unsigned hmask = (round == 0) ? 0u : (0xFFFFFFFFu << (shift + 8));
        for (int i = tid; i < 256; i += NT) hist[i] = 0;
        __syncthreads();
        for (int i = tid; i < 8199; i += NT) {
            unsigned b = __float_as_uint(fabsf(D1[i]));
            if ((b & hmask) == pref) atomicAdd(&hist[(b >> shift) & 255], 1);
        }
        __syncthreads();
        if (tid < 32) {
            int s[8]; int tot = 0;
            #pragma unroll
            for (int j = 0; j < 8; j++) { s[j] = hist[tid * 8 + j]; tot += s[j]; }
            int run = tot;
            #pragma unroll
            for (int off = 1; off < 32; off <<= 1) {
                int n = __shfl_up_sync(0xFFFFFFFFu, run, off);
                if (tid >= (unsigned)off) run += n;
            }
            int excl = run - tot;
            if (kk >= excl && kk < excl + tot) {
                int acc = excl;
                #pragma unroll
                for (int j = 0; j < 8; j++) {
                    if (acc + s[j] > kk) {
                        hist[256] = (int)(pref | ((unsigned)(tid * 8 + j) << shift));
                        hist[257] = kk - acc;
                        break;
                    }
                    acc += s[j];
                }
            }
        }
        __syncthreads();
        pref = (unsigned)hist[256];
        kk   = hist[257];
    }
    const float med = __uint_as_float(pref);
    const float thr = (med / 0.6745f) * 4.4054649f;   // sqrt(2*ln(16384))

    // inverse DWT with fused soft-thresholding, reusing dead regions
    inv_level(A4, D4, E3, 2061, thr, tid);
    inv_level(E3, D3, E2, 4107, thr, tid);
    inv_level(E2, D2, E1, 8199, thr, tid);
    inv_final(E1, D1, out + (size_t)row * 16384, thr, tid);
}

extern "C" void kernel_launch(void* const* d_in, const int* in_sizes, int n_in,
                              void* d_out, int out_size)
{
    const float* x = (const float*)d_in[0];
    float* out = (float*)d_out;
    const int rows = in_sizes[0] / 16384;   // 128*16 = 2048
    cudaFuncSetAttribute(wden_kernel, cudaFuncAttributeMaxDynamicSharedMemorySize, SMEM_BYTES);
    wden_kernel<<<rows, NT, SMEM_BYTES>>>(x, out, rows);
}